// round 1
// baseline (speedup 1.0000x reference)
#include <cuda_runtime.h>
#include <math.h>
#include <stdint.h>

#define BATCH   65536
#define IN_DIM  512
#define LATENT  32
#define NTRI    528
#define NPAD    544            // padded tri/elts row (544 % 32 == 0, room for chunk 16 garbage)
#define WENC_PAD 524           // 524 % 32 == 12 -> conflict-free float4 rows
#define THREADS 256
#define WARPS   8
#define RPW     4              // rows per warp per tile
#define TILE_ROWS (WARPS*RPW)  // 32
#define NTILES  (BATCH/TILE_ROWS) // 2048
#define GRID    304

// ---- smem layout (floats) ----
#define OFF_WENC 0
#define SZ_WENC  (LATENT*WENC_PAD)              // 16768
#define OFF_WCH  (OFF_WENC + SZ_WENC)           // 16768
#define SZ_WCH   (LATENT*NPAD)                  // 17408
#define OFF_WMU  (OFF_WCH + SZ_WCH)             // 34176
#define OFF_BENC (OFF_WMU + LATENT*LATENT)      // 35200
#define OFF_BMU  (OFF_BENC + 32)                // 35232
#define OFF_BCH  (OFF_BMU + 32)                 // 35264
#define OFF_S    (OFF_BCH + NPAD)               // 35808
#define OFF_XBUF (OFF_S + 32)                   // 35840 (16B aligned)
#define SMEM_FLOATS (OFF_XBUF + WARPS*RPW*NPAD) // 53248 floats = 212992 B

#define MU_OFF  ((size_t)BATCH*LATENT)
#define COV_OFF ((size_t)BATCH*LATENT*2)

__device__ __forceinline__ float lrelu(float v) { return v >= 0.f ? v : 0.01f * v; }

__global__ void __launch_bounds__(THREADS)
pm_kernel(const float* __restrict__ x,       const float* __restrict__ W_enc,
          const float* __restrict__ b_enc,   const float* __restrict__ bn_gamma,
          const float* __restrict__ bn_beta, const float* __restrict__ bn_mean,
          const float* __restrict__ bn_var,  const float* __restrict__ W_mu,
          const float* __restrict__ b_mu,    const float* __restrict__ W_ch,
          const float* __restrict__ b_ch,    float* __restrict__ out)
{
    extern __shared__ float sm[];
    const int tid = threadIdx.x;

    // ---- stage + fold weights into smem ----
    if (tid < 32) {
        float s = bn_gamma[tid] * rsqrtf(bn_var[tid] + 1e-5f);
        sm[OFF_S + tid]    = s;
        sm[OFF_BENC + tid] = (b_enc[tid] - bn_mean[tid]) * s + bn_beta[tid];
        sm[OFF_BMU + tid]  = b_mu[tid];
    }
    __syncthreads();
    for (int idx = tid; idx < IN_DIM * LATENT; idx += THREADS) {
        int k = idx >> 5, j = idx & 31;
        sm[OFF_WENC + j * WENC_PAD + k] = W_enc[idx] * sm[OFF_S + j];  // transposed + BN fold
    }
    for (int idx = tid; idx < LATENT * NPAD; idx += THREADS) {
        int k = idx / NPAD, c = idx - k * NPAD;
        sm[OFF_WCH + idx] = (c < NTRI) ? W_ch[k * NTRI + c] : 0.f;
    }
    for (int idx = tid; idx < LATENT * LATENT; idx += THREADS) sm[OFF_WMU + idx] = W_mu[idx];
    for (int idx = tid; idx < NPAD; idx += THREADS)            sm[OFF_BCH + idx] = (idx < NTRI) ? b_ch[idx] : 0.f;
    __syncthreads();

    const int warp = tid >> 5, lane = tid & 31;
    float* xw = sm + OFF_XBUF + warp * (RPW * NPAD);        // x tile, later reused for L (packed tri)
    const float* wrow = sm + OFF_WENC + lane * WENC_PAD;

    for (int tile = blockIdx.x; tile < NTILES; tile += gridDim.x) {
        const int rbase = tile * TILE_ROWS + warp * RPW;

        // ---- load x[4][512] into per-warp smem (coalesced float4) ----
        #pragma unroll
        for (int r = 0; r < RPW; r++) {
            const float4* xg = (const float4*)(x + (size_t)(rbase + r) * IN_DIM);
            #pragma unroll
            for (int c = 0; c < 4; c++) {
                float4 v = xg[c * 32 + lane];
                *(float4*)(xw + r * NPAD + c * 128 + lane * 4) = v;
            }
        }
        __syncwarp();

        // ---- enc GEMM: h[r] for col=lane ----
        float h0 = 0.f, h1 = 0.f, h2 = 0.f, h3 = 0.f;
        #pragma unroll 4
        for (int k = 0; k < IN_DIM; k += 4) {
            float4 wv = *(const float4*)(wrow + k);
            float4 a0 = *(const float4*)(xw + 0 * NPAD + k);
            float4 a1 = *(const float4*)(xw + 1 * NPAD + k);
            float4 a2 = *(const float4*)(xw + 2 * NPAD + k);
            float4 a3 = *(const float4*)(xw + 3 * NPAD + k);
            h0 = fmaf(a0.x, wv.x, h0); h0 = fmaf(a0.y, wv.y, h0); h0 = fmaf(a0.z, wv.z, h0); h0 = fmaf(a0.w, wv.w, h0);
            h1 = fmaf(a1.x, wv.x, h1); h1 = fmaf(a1.y, wv.y, h1); h1 = fmaf(a1.z, wv.z, h1); h1 = fmaf(a1.w, wv.w, h1);
            h2 = fmaf(a2.x, wv.x, h2); h2 = fmaf(a2.y, wv.y, h2); h2 = fmaf(a2.z, wv.z, h2); h2 = fmaf(a2.w, wv.w, h2);
            h3 = fmaf(a3.x, wv.x, h3); h3 = fmaf(a3.y, wv.y, h3); h3 = fmaf(a3.z, wv.z, h3); h3 = fmaf(a3.w, wv.w, h3);
        }
        {
            float bj = sm[OFF_BENC + lane];
            h0 = lrelu(h0 + bj); h1 = lrelu(h1 + bj); h2 = lrelu(h2 + bj); h3 = lrelu(h3 + bj);
            out[(size_t)(rbase + 0) * 32 + lane] = h0;
            out[(size_t)(rbase + 1) * 32 + lane] = h1;
            out[(size_t)(rbase + 2) * 32 + lane] = h2;
            out[(size_t)(rbase + 3) * 32 + lane] = h3;
        }

        // ---- mu + ch GEMMs over k=0..31 via warp-broadcast of h ----
        float amu0 = 0.f, amu1 = 0.f, amu2 = 0.f, amu3 = 0.f;
        float ac[RPW][17];
        #pragma unroll
        for (int r = 0; r < RPW; r++)
            #pragma unroll
            for (int c = 0; c < 17; c++) ac[r][c] = 0.f;

        #pragma unroll 2
        for (int k = 0; k < LATENT; k++) {
            float hv0 = __shfl_sync(0xffffffffu, h0, k);
            float hv1 = __shfl_sync(0xffffffffu, h1, k);
            float hv2 = __shfl_sync(0xffffffffu, h2, k);
            float hv3 = __shfl_sync(0xffffffffu, h3, k);
            float wm = sm[OFF_WMU + k * 32 + lane];
            amu0 = fmaf(hv0, wm, amu0); amu1 = fmaf(hv1, wm, amu1);
            amu2 = fmaf(hv2, wm, amu2); amu3 = fmaf(hv3, wm, amu3);
            const float* wck = sm + OFF_WCH + k * NPAD + lane;
            #pragma unroll
            for (int c = 0; c < 17; c++) {
                float wc = wck[c * 32];
                ac[0][c] = fmaf(hv0, wc, ac[0][c]);
                ac[1][c] = fmaf(hv1, wc, ac[1][c]);
                ac[2][c] = fmaf(hv2, wc, ac[2][c]);
                ac[3][c] = fmaf(hv3, wc, ac[3][c]);
            }
        }
        {
            float bm = sm[OFF_BMU + lane];
            out[MU_OFF + (size_t)(rbase + 0) * 32 + lane] = lrelu(amu0 + bm);
            out[MU_OFF + (size_t)(rbase + 1) * 32 + lane] = lrelu(amu1 + bm);
            out[MU_OFF + (size_t)(rbase + 2) * 32 + lane] = lrelu(amu2 + bm);
            out[MU_OFF + (size_t)(rbase + 3) * 32 + lane] = lrelu(amu3 + bm);
        }

        // ---- elts -> packed-tri L in smem (reuse x buffer; x is dead) ----
        __syncwarp();
        #pragma unroll
        for (int c = 0; c < 17; c++) {
            float bc = sm[OFF_BCH + c * 32 + lane];
            #pragma unroll
            for (int r = 0; r < RPW; r++)
                xw[r * NPAD + c * 32 + lane] = lrelu(ac[r][c] + bc);
        }
        __syncwarp();
        // diag transform: lane handles diag of L-row 'lane'
        {
            int dj = ((lane * (lane + 1)) >> 1) + lane;
            #pragma unroll 1
            for (int r = 0; r < RPW; r++) {
                float d = xw[r * NPAD + dj];
                float sp = (d > 20.f) ? d : log1pf(expf(d));
                sp = fminf(fmaxf(sp, 0.001f), 100.f) + 0.01f;
                xw[r * NPAD + dj] = sp;
            }
        }
        __syncwarp();

        // ---- cov = L L^T + 0.01 I ; lane = output column k ----
        const int kbase = (lane * (lane + 1)) >> 1;
        #pragma unroll 1
        for (int r = 0; r < RPW; r++) {
            const float* Lr = xw + r * NPAD;
            float Lk[32];
            #pragma unroll
            for (int j = 0; j < 32; j++) {
                float v = Lr[kbase + j];               // conflict-free: tri(k) mod 32 is a permutation
                Lk[j] = (j <= lane) ? v : 0.f;
            }
            float* oc = out + COV_OFF + (size_t)(rbase + r) * 1024;
            #pragma unroll
            for (int i = 0; i < 32; i++) {
                float a0 = 0.f, a1 = 0.f, a2 = 0.f, a3 = 0.f;
                #pragma unroll
                for (int j = 0; j <= i; j++) {
                    float lv = Lr[(i * (i + 1)) / 2 + j];   // broadcast, immediate offset
                    if      ((j & 3) == 0) a0 = fmaf(Lk[j], lv, a0);
                    else if ((j & 3) == 1) a1 = fmaf(Lk[j], lv, a1);
                    else if ((j & 3) == 2) a2 = fmaf(Lk[j], lv, a2);
                    else                   a3 = fmaf(Lk[j], lv, a3);
                }
                float cv = (a0 + a1) + (a2 + a3);
                if (lane == i) cv += 0.01f;
                oc[i * 32 + lane] = cv;
            }
        }
        __syncwarp();   // protect xw before next tile's x load
    }
}

extern "C" void kernel_launch(void* const* d_in, const int* in_sizes, int n_in,
                              void* d_out, int out_size)
{
    (void)in_sizes; (void)n_in; (void)out_size;
    const float* x        = (const float*)d_in[0];
    const float* W_enc    = (const float*)d_in[1];
    const float* b_enc    = (const float*)d_in[2];
    const float* bn_gamma = (const float*)d_in[3];
    const float* bn_beta  = (const float*)d_in[4];
    const float* bn_mean  = (const float*)d_in[5];
    const float* bn_var   = (const float*)d_in[6];
    const float* W_mu     = (const float*)d_in[7];
    const float* b_mu     = (const float*)d_in[8];
    const float* W_ch     = (const float*)d_in[9];
    const float* b_ch     = (const float*)d_in[10];
    float* out = (float*)d_out;

    cudaFuncSetAttribute(pm_kernel, cudaFuncAttributeMaxDynamicSharedMemorySize,
                         SMEM_FLOATS * (int)sizeof(float));
    pm_kernel<<<GRID, THREADS, SMEM_FLOATS * sizeof(float)>>>(
        x, W_enc, b_enc, bn_gamma, bn_beta, bn_mean, bn_var,
        W_mu, b_mu, W_ch, b_ch, out);
}